// round 6
// baseline (speedup 1.0000x reference)
#include <cuda_runtime.h>
#include <math.h>

#define B      64
#define T      200
#define Q      4096
#define Q2     (2*Q)
#define TM1    (T-1)            // 199
#define NROW   (B*TM1)          // 12736
#define NPROBE 12               // probe rows s = 16, 32, ..., 192
#define NPB    (B*NPROBE)       // 768 probe blocks
#define NBLK   (NPB + NROW)     // 13504 total blocks

// Scratch (no device allocation allowed)
__device__ float    g_p[NROW];
__device__ float    g_a[NROW];
__device__ int      g_flag[NROW];
__device__ unsigned g_pb[B];     // bits 0..11: probe-k done, bits 16..27: probe-k valid
__device__ float    g_lossb[B];
__device__ int      g_count;     // zero-initialized; last block resets it

// ---------------------------------------------------------------------------
__device__ __forceinline__ void store_row(const float* __restrict__ pred,
                                          int b, int t, int j)
{
    if (threadIdx.x == 0) {
        float p = 0.0f, a = 0.0f;
        int fl = 0;
        if (j >= 0) {
            const int q = j & (Q - 1);
            a  = (j < Q) ? 1.0f : 0.0f;
            p  = __ldg(pred + ((size_t)b * T + t) * (size_t)Q + q);
            fl = 1;
        }
        const int row = b * TM1 + t;
        g_p[row]    = p;
        g_a[row]    = a;
        g_flag[row] = fl;
    }
}

__device__ __forceinline__ int check4(float4 v, int vi, int f)
{
    if (v.x != 0.0f) f = vi * 4 + 0;
    if (v.y != 0.0f) f = vi * 4 + 1;
    if (v.z != 0.0f) f = vi * 4 + 2;
    if (v.w != 0.0f) f = vi * 4 + 3;
    return f;
}

// Release-add on the completion counter: orders this thread's prior STGs to
// gpu scope WITHOUT a chip-wide L1 flush (no CCTL.IVALL storm — R4 lesson).
__device__ __forceinline__ int release_add_count()
{
    int old;
    asm volatile("atom.add.release.gpu.u32 %0, [%1], 1;"
                 : "=r"(old) : "l"(&g_count) : "memory");
    return old;
}

// ---------------------------------------------------------------------------
// Two-stage row scan: first half-row (MLP=4), test; only if not found, second
// half. <=2 barriers per row.
// ---------------------------------------------------------------------------
__device__ __forceinline__ int scan_row2(const float* __restrict__ batch,
                                         int b, int s)
{
    const float4* __restrict__ base =
        reinterpret_cast<const float4*>(batch + ((size_t)b * T + s) * (size_t)Q2);
    const int tid = threadIdx.x;

    __shared__ int s_idx;
    if (tid == 0) s_idx = -1;
    __syncthreads();

    float4 v0 = base[tid];
    float4 v1 = base[256 + tid];
    float4 v2 = base[512 + tid];
    float4 v3 = base[768 + tid];
    int f = -1;
    f = check4(v0, tid, f);
    f = check4(v1, 256 + tid, f);
    f = check4(v2, 512 + tid, f);
    f = check4(v3, 768 + tid, f);
    if (f >= 0) s_idx = f;

    if (!__syncthreads_or(f >= 0)) {
        v0 = base[1024 + tid];
        v1 = base[1280 + tid];
        v2 = base[1536 + tid];
        v3 = base[1792 + tid];
        f = -1;
        f = check4(v0, 1024 + tid, f);
        f = check4(v1, 1280 + tid, f);
        f = check4(v2, 1536 + tid, f);
        f = check4(v3, 1792 + tid, f);
        if (f >= 0) s_idx = f;
        __syncthreads();
    }
    return s_idx;
}

// ---------------------------------------------------------------------------
// Epilogue (runs in the single last block). Warp w handles batches w, w+8,...
// All reads via __ldcg (L2 is the coherence point for the producers' STGs,
// ordered by their release-adds). Deterministic fixed-order reductions.
// Output layout: [0]=loss, [1..1+N)=p*maskf, [1+N..1+2N)=a*maskf,
//                [1+2N..1+3N)=mask, N = B*TM1.
// ---------------------------------------------------------------------------
__device__ void run_epilogue(const int* __restrict__ isTestP,
                             const int* __restrict__ tslP,
                             float* __restrict__ d_out)
{
    const int tid  = threadIdx.x;
    const int warp = tid >> 5;
    const int lane = tid & 31;
    const int isTest = *isTestP;
    const int tsl    = *tslP;

    for (int b = warp; b < B; b += 8) {
        int myLast = -1;
        for (int t = lane; t < TM1; t += 32)
            if (__ldcg(&g_flag[b * TM1 + t]) > 0) myLast = t;  // increasing t
        #pragma unroll
        for (int off = 16; off > 0; off >>= 1)
            myLast = max(myLast, __shfl_xor_sync(0xffffffffu, myLast, off));
        const int last = max(myLast, 0);

        int start = 0;
        if (isTest) {
            const int length = last + 1;
            start = (length > tsl) ? (length - tsl) : 0;
        }
        const float cnt = (float)(last - start + 1);

        float sum = 0.0f;
        for (int t = lane; t < TM1; t += 32) {
            const int idx = b * TM1 + t;
            const float p = __ldcg(&g_p[idx]);
            const float a = __ldcg(&g_a[idx]);
            const float maskf = (t >= start && t <= last) ? 1.0f : 0.0f;
            const float logp = fmaxf(logf(p), -100.0f);
            const float l1mp = fmaxf(log1pf(-p), -100.0f);
            sum += -(a * logp + (1.0f - a) * l1mp) * maskf;

            d_out[1 + idx]            = p * maskf;
            d_out[1 + NROW + idx]     = a * maskf;
            d_out[1 + 2 * NROW + idx] = maskf;
        }
        #pragma unroll
        for (int off = 16; off > 0; off >>= 1)
            sum += __shfl_xor_sync(0xffffffffu, sum, off);
        if (lane == 0) g_lossb[b] = sum / cnt;
    }
    __syncthreads();

    __shared__ float s2[64];
    if (tid < 64) s2[tid] = g_lossb[tid];
    __syncthreads();
    #pragma unroll
    for (int off = 32; off > 0; off >>= 1) {
        if (tid < off) s2[tid] += s2[tid + off];
        __syncthreads();
    }
    // resets for next graph replay + final output
    if (tid < B) g_pb[tid] = 0u;
    if (tid == 0) {
        d_out[0] = s2[0];
        g_count  = 0;
    }
}

// ---------------------------------------------------------------------------
// Fused kernel: blocks [0, NPB) probe, blocks [NPB, NBLK) scan. Last block
// (by completion count) runs the epilogue.
// ---------------------------------------------------------------------------
__global__ __launch_bounds__(256)
void fused_kernel(const float* __restrict__ pred,
                  const float* __restrict__ batch,
                  const int*   __restrict__ isTestP,
                  const int*   __restrict__ tslP,
                  float*       __restrict__ d_out)
{
    const int bid = blockIdx.x;
    const int tid = threadIdx.x;

    if (bid < NPB) {
        // ---- probe block: full-row read at MLP=8, one barrier ----
        const int b = bid / NPROBE;
        const int k = bid % NPROBE;
        const int s = 16 * (k + 1);
        const float4* __restrict__ base =
            reinterpret_cast<const float4*>(batch + ((size_t)b * T + s) * (size_t)Q2);

        __shared__ int s_idx;
        if (tid == 0) s_idx = -1;
        __syncthreads();

        float4 v[8];
        #pragma unroll
        for (int c = 0; c < 8; ++c) v[c] = base[c * 256 + tid];
        int f = -1;
        #pragma unroll
        for (int c = 0; c < 8; ++c) f = check4(v[c], c * 256 + tid, f);
        if (f >= 0) s_idx = f;
        __syncthreads();

        store_row(pred, b, s - 1, s_idx);
        if (tid == 0) {
            const unsigned bits =
                (1u << k) | ((s_idx >= 0) ? (1u << (16 + k)) : 0u);
            atomicOr(&g_pb[b], bits);       // L2-point publish, no fence
        }
    } else {
        // ---- scan block ----
        const int row = bid - NPB;
        const int b   = row / TM1;
        const int t   = row % TM1;
        const int s   = t + 1;
        const bool probeRow = (s <= 192 && (s & 15) == 0);

        if (!probeRow) {
            // Poll probe word for this batch (bounded spin; fallback = full scan)
            __shared__ unsigned s_v;
            if (tid == 0) {
                unsigned v = 0;
                int it = 0;
                do {
                    asm volatile("ld.global.cg.u32 %0, [%1];"
                                 : "=r"(v) : "l"(&g_pb[b]) : "memory");
                    if ((v & 0xFFFu) == 0xFFFu) break;
                    __nanosleep(64);
                } while (++it < 50000);
                s_v = v;
            }
            __syncthreads();
            const unsigned v = s_v;

            int ub = 200;                    // fallback: scan everything
            if ((v & 0xFFFu) == 0xFFFu) {
                #pragma unroll
                for (int k = NPROBE - 1; k >= 0; --k)
                    if (!((v >> (16 + k)) & 1u)) ub = 16 * (k + 1);
            }

            if (s >= ub) {
                store_row(pred, b, t, -1);   // provably all-zero: no reads
            } else {
                const int j = scan_row2(batch, b, s);
                store_row(pred, b, t, j);
            }
        }
    }

    // ---- completion: last block runs the epilogue ----
    __shared__ bool s_last;
    if (tid == 0) s_last = (release_add_count() == NBLK - 1);
    __syncthreads();
    if (s_last) {
        asm volatile("fence.acq_rel.gpu;" ::: "memory");  // one acquire, one block
        run_epilogue(isTestP, tslP, d_out);
    }
}

extern "C" void kernel_launch(void* const* d_in, const int* in_sizes, int n_in,
                              void* d_out, int out_size)
{
    const float* pred  = (const float*)d_in[0];
    const float* batch = (const float*)d_in[1];
    const int*   isT   = (const int*)d_in[2];
    const int*   tsl   = (const int*)d_in[3];
    float*       out   = (float*)d_out;

    fused_kernel<<<NBLK, 256>>>(pred, batch, isT, tsl, out);
}

// round 7
// speedup vs baseline: 2.0386x; 2.0386x over previous
#include <cuda_runtime.h>
#include <math.h>

#define B      64
#define T      200
#define Q      4096
#define Q2     (2*Q)
#define TM1    (T-1)            // 199
#define NROW   (B*TM1)          // 12736
#define NPROBE 12               // probe rows s = 16, 32, ..., 192
#define NPB    (B*NPROBE)       // 768 probe blocks
#define NBLK   (NPB + NROW)     // 13504 blocks in the fused launch

// Scratch (no device allocation allowed)
__device__ float    g_p[NROW];
__device__ float    g_a[NROW];
__device__ int      g_flag[NROW];
__device__ unsigned g_pb[B];     // bits 0..11 probe-done, bits 16..27 probe-valid
__device__ float    g_lossb[B];
__device__ int      g_count;     // used only by the 64-block epilogue

// ---------------------------------------------------------------------------
__device__ __forceinline__ void store_row(const float* __restrict__ pred,
                                          int b, int t, int j)
{
    if (threadIdx.x == 0) {
        float p = 0.0f, a = 0.0f;
        int fl = 0;
        if (j >= 0) {
            const int q = j & (Q - 1);
            a  = (j < Q) ? 1.0f : 0.0f;
            p  = __ldg(pred + ((size_t)b * T + t) * (size_t)Q + q);
            fl = 1;
        }
        const int row = b * TM1 + t;
        g_p[row]    = p;
        g_a[row]    = a;
        g_flag[row] = fl;
    }
}

__device__ __forceinline__ int check4(float4 v, int vi, int f)
{
    if (v.x != 0.0f) f = vi * 4 + 0;
    if (v.y != 0.0f) f = vi * 4 + 1;
    if (v.z != 0.0f) f = vi * 4 + 2;
    if (v.w != 0.0f) f = vi * 4 + 3;
    return f;
}

// ---------------------------------------------------------------------------
// Pipelined early-exit scan (R3, proven 5 TB/s): chunk c+1's load is issued
// before the barrier deciding exit on chunk c. Over-reads <= one 4 KB chunk.
// ---------------------------------------------------------------------------
__device__ __forceinline__ int scan_row(const float* __restrict__ batch,
                                        int b, int s)
{
    const float4* __restrict__ base =
        reinterpret_cast<const float4*>(batch + ((size_t)b * T + s) * (size_t)Q2);
    const int tid = threadIdx.x;

    __shared__ int s_idx;
    if (tid == 0) s_idx = -1;
    __syncthreads();

    float4 cur = base[tid];
    #pragma unroll 1
    for (int c = 0; c < 8; ++c) {
        float4 nxt = make_float4(0.f, 0.f, 0.f, 0.f);
        if (c < 7) nxt = base[(c + 1) * 256 + tid];

        int f = check4(cur, c * 256 + tid, -1);
        if (f >= 0) s_idx = f;
        if (__syncthreads_or(f >= 0)) break;
        cur = nxt;
    }
    return s_idx;
}

// ---------------------------------------------------------------------------
// K1 (fused): bids [0,768) probe, bids [768, NBLK) scan.
// NO per-block gpu-scope fences or release atomics (R4+R6 lesson: at grid
// ~13k they cap the chip at ~2.2 TB/s). Probe publishes per-batch bits with a
// plain atomicOr (L2-point); scan polls with ld.global.cg (L2-coherent),
// bounded spin + full-scan fallback => deadlock-free and always correct.
// ---------------------------------------------------------------------------
__global__ __launch_bounds__(256)
void fused_kernel(const float* __restrict__ pred,
                  const float* __restrict__ batch)
{
    const int bid = blockIdx.x;
    const int tid = threadIdx.x;

    if (bid < NPB) {
        // ---- probe block: full-row read at MLP=8, one barrier ----
        const int b = bid / NPROBE;
        const int k = bid % NPROBE;
        const int s = 16 * (k + 1);
        const float4* __restrict__ base =
            reinterpret_cast<const float4*>(batch + ((size_t)b * T + s) * (size_t)Q2);

        __shared__ int s_idx;
        if (tid == 0) s_idx = -1;
        __syncthreads();

        float4 v[8];
        #pragma unroll
        for (int c = 0; c < 8; ++c) v[c] = base[c * 256 + tid];
        int f = -1;
        #pragma unroll
        for (int c = 0; c < 8; ++c) f = check4(v[c], c * 256 + tid, f);
        if (f >= 0) s_idx = f;
        __syncthreads();

        store_row(pred, b, s - 1, s_idx);
        if (tid == 0) {
            const unsigned bits =
                (1u << k) | ((s_idx >= 0) ? (1u << (16 + k)) : 0u);
            atomicOr(&g_pb[b], bits);            // plain L2 publish, no fence
        }
        return;
    }

    // ---- scan block ----
    const int row = bid - NPB;
    const int b   = row / TM1;
    const int t   = row % TM1;
    const int s   = t + 1;
    if (s <= 192 && (s & 15) == 0) return;       // row handled by a probe block

    __shared__ unsigned s_v;
    if (tid == 0) {
        unsigned v = 0;
        int it = 0;
        do {
            asm volatile("ld.global.cg.u32 %0, [%1];"
                         : "=r"(v) : "l"(&g_pb[b]) : "memory");
            if ((v & 0xFFFu) == 0xFFFu) break;
            __nanosleep(128);
        } while (++it < 20000);
        s_v = v;
    }
    __syncthreads();
    const unsigned v = s_v;

    int ub = 200;                                // fallback: scan everything
    if ((v & 0xFFFu) == 0xFFFu) {
        #pragma unroll
        for (int k = NPROBE - 1; k >= 0; --k)
            if (!((v >> (16 + k)) & 1u)) ub = 16 * (k + 1);
    }

    if (s >= ub) {
        store_row(pred, b, t, -1);               // provably all-zero: no reads
    } else {
        const int j = scan_row(batch, b, s);
        store_row(pred, b, t, j);
    }
}

// ---------------------------------------------------------------------------
// K2: epilogue, grid=64 (fence/atomic cost negligible at this scale — R3/R5
// measured). Also resets g_pb for the next graph replay.
// Output layout: [0]=loss, [1..1+N)=p*maskf, [1+N..1+2N)=a*maskf,
//                [1+2N..1+3N)=mask, N = B*TM1.
// ---------------------------------------------------------------------------
__global__ __launch_bounds__(256)
void epilogue_kernel(const int* __restrict__ isTestP,
                     const int* __restrict__ tslP,
                     float* __restrict__ d_out)
{
    const int b   = blockIdx.x;
    const int tid = threadIdx.x;

    float p = 0.0f, a = 0.0f;
    int myLast = -1;
    if (tid < TM1) {
        const int idx = b * TM1 + tid;
        p = g_p[idx];
        a = g_a[idx];
        if (g_flag[idx] > 0) myLast = tid;
    }

    __shared__ int s_i[256];
    s_i[tid] = myLast;
    __syncthreads();
    #pragma unroll
    for (int off = 128; off > 0; off >>= 1) {
        if (tid < off) s_i[tid] = max(s_i[tid], s_i[tid + off]);
        __syncthreads();
    }
    const int last = max(s_i[0], 0);

    int start = 0;
    if (*isTestP) {
        const int length = last + 1;
        const int tsl = *tslP;
        start = (length > tsl) ? (length - tsl) : 0;
    }

    const bool  m     = (tid < TM1) && (tid >= start) && (tid <= last);
    const float maskf = m ? 1.0f : 0.0f;
    const float cnt   = (float)(last - start + 1);

    float bce = 0.0f;
    if (tid < TM1) {
        const float logp = fmaxf(logf(p), -100.0f);
        const float l1mp = fmaxf(log1pf(-p), -100.0f);
        bce = -(a * logp + (1.0f - a) * l1mp);

        const int idx = b * TM1 + tid;
        d_out[1 + idx]            = p * maskf;
        d_out[1 + NROW + idx]     = a * maskf;
        d_out[1 + 2 * NROW + idx] = maskf;
    }

    __shared__ float s_f[256];
    s_f[tid] = bce * maskf;
    __syncthreads();
    #pragma unroll
    for (int off = 128; off > 0; off >>= 1) {
        if (tid < off) s_f[tid] += s_f[tid + off];
        __syncthreads();
    }

    __shared__ bool s_last;
    if (tid == 0) {
        g_lossb[b] = s_f[0] / cnt;
        g_pb[b]    = 0u;                         // reset for next replay
        __threadfence();
        s_last = (atomicAdd(&g_count, 1) == B - 1);
    }
    __syncthreads();

    if (s_last) {
        __shared__ float s2[64];
        if (tid < B) s2[tid] = g_lossb[tid];
        __syncthreads();
        #pragma unroll
        for (int off = 32; off > 0; off >>= 1) {
            if (tid < off) s2[tid] += s2[tid + off];
            __syncthreads();
        }
        if (tid == 0) {
            d_out[0] = s2[0];
            g_count  = 0;                        // reset for next replay
        }
    }
}

extern "C" void kernel_launch(void* const* d_in, const int* in_sizes, int n_in,
                              void* d_out, int out_size)
{
    const float* pred  = (const float*)d_in[0];
    const float* batch = (const float*)d_in[1];
    const int*   isT   = (const int*)d_in[2];
    const int*   tsl   = (const int*)d_in[3];
    float*       out   = (float*)d_out;

    fused_kernel<<<NBLK, 256>>>(pred, batch);
    epilogue_kernel<<<B, 256>>>(isT, tsl, out);
}